// round 10
// baseline (speedup 1.0000x reference)
#include <cuda_runtime.h>
#include <math.h>

#define DD 4096
#define NF4 (DD / 4)          // 1024 float4 per row
#define NT 256                // 8 warps per block
#define NBLK 512              // 4096 warps; <=4 blocks/SM so all co-resident

__device__ float g_xk[DD], g_xv[DD], g_xr[DD];
__device__ float g_k[DD], g_v[DD], g_r[DD], g_rv[DD];
__device__ unsigned g_count = 0;
__device__ volatile unsigned g_sense = 0;

__device__ __forceinline__ float dot4(float4 a, float4 b) {
    float s = a.x * b.x;
    s = fmaf(a.y, b.y, s);
    s = fmaf(a.z, b.z, s);
    s = fmaf(a.w, b.w, s);
    return s;
}

__global__ void mix_kernel(const float* __restrict__ x,
                           const float* __restrict__ sxx,
                           const float* __restrict__ tmk,
                           const float* __restrict__ tmv,
                           const float* __restrict__ tmr) {
    int i = blockIdx.x * blockDim.x + threadIdx.x;   // float4 index
    if (i >= NF4) return;
    float4 xi = ((const float4*)x)[i];
    float4 si = ((const float4*)sxx)[i];
    float4 k = ((const float4*)tmk)[i];
    float4 v = ((const float4*)tmv)[i];
    float4 r = ((const float4*)tmr)[i];
    float4 ok, ov, orr;
    ok.x = fmaf(xi.x - si.x, k.x, si.x);  ok.y = fmaf(xi.y - si.y, k.y, si.y);
    ok.z = fmaf(xi.z - si.z, k.z, si.z);  ok.w = fmaf(xi.w - si.w, k.w, si.w);
    ov.x = fmaf(xi.x - si.x, v.x, si.x);  ov.y = fmaf(xi.y - si.y, v.y, si.y);
    ov.z = fmaf(xi.z - si.z, v.z, si.z);  ov.w = fmaf(xi.w - si.w, v.w, si.w);
    orr.x = fmaf(xi.x - si.x, r.x, si.x); orr.y = fmaf(xi.y - si.y, r.y, si.y);
    orr.z = fmaf(xi.z - si.z, r.z, si.z); orr.w = fmaf(xi.w - si.w, r.w, si.w);
    ((float4*)g_xk)[i] = ok;
    ((float4*)g_xv)[i] = ov;
    ((float4*)g_xr)[i] = orr;
}

__global__ void __launch_bounds__(NT, 4) fused_kernel(
        const float* __restrict__ wk, const float* __restrict__ wv,
        const float* __restrict__ wr, const float* __restrict__ wo,
        const float* __restrict__ x,
        const float* __restrict__ aa, const float* __restrict__ bb,
        const float* __restrict__ pp,
        const float* __restrict__ t_decay, const float* __restrict__ t_first,
        float* __restrict__ out) {
    const int lane  = threadIdx.x & 31;
    const int warp  = threadIdx.x >> 5;
    const int row   = blockIdx.x * 8 + warp;       // 0..4095
    __shared__ int s_last;

    // ---------------- phase 1: k, v, r matvecs (3 interleaved streams/warp)
    {
        const float4* Ak = (const float4*)(wk + (size_t)row * DD);
        const float4* Av = (const float4*)(wv + (size_t)row * DD);
        const float4* Ar = (const float4*)(wr + (size_t)row * DD);
        const float4* Bk = (const float4*)g_xk;
        const float4* Bv = (const float4*)g_xv;
        const float4* Br = (const float4*)g_xr;

        float sk = 0.f, sv = 0.f, sr = 0.f;
        #pragma unroll 2
        for (int j = lane; j < NF4; j += 32) {
            float4 ak = __ldcs(&Ak[j]);
            float4 av = __ldcs(&Av[j]);
            float4 ar = __ldcs(&Ar[j]);
            float4 bk = __ldg(&Bk[j]);
            float4 bv = __ldg(&Bv[j]);
            float4 br = __ldg(&Br[j]);
            sk += dot4(ak, bk);
            sv += dot4(av, bv);
            sr += dot4(ar, br);
        }
        #pragma unroll
        for (int o = 16; o; o >>= 1) {
            sk += __shfl_xor_sync(0xffffffffu, sk, o);
            sv += __shfl_xor_sync(0xffffffffu, sv, o);
            sr += __shfl_xor_sync(0xffffffffu, sr, o);
        }
        if (lane == 0) {
            g_k[row] = sk;
            g_v[row] = sv;
            g_r[row] = 1.0f / (1.0f + expf(-sr));
        }
    }

    // ---------------- barrier; last block to arrive runs WKV, then releases
    {
        __syncthreads();
        unsigned s;
        if (threadIdx.x == 0) {
            s = g_sense;
            __threadfence();
            unsigned old = atomicAdd(&g_count, 1u);
            s_last = (old == NBLK - 1) ? 1 : 0;
        }
        __syncthreads();
        if (s_last) {
            // this block computes the elementwise WKV for all DD elements
            for (int i = threadIdx.x; i < DD; i += NT) {
                float k = g_k[i], v = g_v[i], r = g_r[i];
                float ppi = pp[i], aai = aa[i], bbi = bb[i];

                float ww = t_first[i] + k;
                float p  = fmaxf(ppi, ww);
                float e1 = expf(ppi - p);
                float e2 = expf(ww - p);
                float a  = fmaf(e1, aai, e2 * v);
                float b  = fmaf(e1, bbi, e2);
                g_rv[i]  = r * (a / b);

                float ww2 = ppi + t_decay[i];
                float p2  = fmaxf(ww2, k);
                float e1b = expf(ww2 - p2);
                float e2b = expf(k - p2);

                out[DD + i]     = x[i];
                out[2 * DD + i] = fmaf(e1b, aai, e2b * v);
                out[3 * DD + i] = fmaf(e1b, bbi, e2b);
                out[4 * DD + i] = p2;
            }
            __syncthreads();
            if (threadIdx.x == 0) {
                g_count = 0;
                __threadfence();
                g_sense = s + 1;          // release
            }
        } else if (threadIdx.x == 0) {
            while (g_sense == s) __nanosleep(32);
        }
        __syncthreads();
        __threadfence();                   // acquire: see g_rv before phase 3
    }

    // ---------------- phase 3: y = w_out @ g_rv (warp-per-row)
    {
        const float4* A  = (const float4*)(wo + (size_t)row * DD);
        const float4* Bv = (const float4*)g_rv;

        float s = 0.f;
        #pragma unroll 4
        for (int j = lane; j < NF4; j += 32) {
            float4 a = __ldcs(&A[j]);
            float4 b = __ldg(&Bv[j]);
            s += dot4(a, b);
        }
        #pragma unroll
        for (int o = 16; o; o >>= 1) s += __shfl_xor_sync(0xffffffffu, s, o);
        if (lane == 0) out[row] = s;
    }
}

extern "C" void kernel_launch(void* const* d_in, const int* in_sizes, int n_in,
                              void* d_out, int out_size) {
    const float* x       = (const float*)d_in[0];
    const float* sxx     = (const float*)d_in[1];
    const float* aa      = (const float*)d_in[2];
    const float* bb      = (const float*)d_in[3];
    const float* pp      = (const float*)d_in[4];
    const float* w_key   = (const float*)d_in[5];
    const float* w_val   = (const float*)d_in[6];
    const float* w_rec   = (const float*)d_in[7];
    const float* w_out   = (const float*)d_in[8];
    const float* t_decay = (const float*)d_in[9];
    const float* t_first = (const float*)d_in[10];
    const float* t_mix_k = (const float*)d_in[11];
    const float* t_mix_v = (const float*)d_in[12];
    const float* t_mix_r = (const float*)d_in[13];
    float* out = (float*)d_out;

    mix_kernel<<<(NF4 + 255) / 256, 256>>>(x, sxx, t_mix_k, t_mix_v, t_mix_r);
    fused_kernel<<<NBLK, NT>>>(w_key, w_val, w_rec, w_out,
                               x, aa, bb, pp, t_decay, t_first, out);
}

// round 12
// speedup vs baseline: 1.1709x; 1.1709x over previous
#include <cuda_runtime.h>
#include <math.h>

#define DD 4096
#define NF4 (DD / 4)          // 1024 float4 per row

__device__ float g_xk[DD], g_xv[DD], g_xr[DD];
__device__ float g_k[DD], g_v[DD], g_r[DD], g_rv[DD];

__device__ __forceinline__ float dot4(float4 a, float4 b) {
    float s = a.x * b.x;
    s = fmaf(a.y, b.y, s);
    s = fmaf(a.z, b.z, s);
    s = fmaf(a.w, b.w, s);
    return s;
}

// grid 16 x 64: one float4 per thread
__global__ void mix_kernel(const float* __restrict__ x,
                           const float* __restrict__ sxx,
                           const float* __restrict__ tmk,
                           const float* __restrict__ tmv,
                           const float* __restrict__ tmr) {
    int i = blockIdx.x * 64 + threadIdx.x;
    if (i >= NF4) return;
    float4 xi = ((const float4*)x)[i];
    float4 si = ((const float4*)sxx)[i];
    float4 k = ((const float4*)tmk)[i];
    float4 v = ((const float4*)tmv)[i];
    float4 r = ((const float4*)tmr)[i];
    float4 ok, ov, orr;
    ok.x = fmaf(xi.x - si.x, k.x, si.x);  ok.y = fmaf(xi.y - si.y, k.y, si.y);
    ok.z = fmaf(xi.z - si.z, k.z, si.z);  ok.w = fmaf(xi.w - si.w, k.w, si.w);
    ov.x = fmaf(xi.x - si.x, v.x, si.x);  ov.y = fmaf(xi.y - si.y, v.y, si.y);
    ov.z = fmaf(xi.z - si.z, v.z, si.z);  ov.w = fmaf(xi.w - si.w, v.w, si.w);
    orr.x = fmaf(xi.x - si.x, r.x, si.x); orr.y = fmaf(xi.y - si.y, r.y, si.y);
    orr.z = fmaf(xi.z - si.z, r.z, si.z); orr.w = fmaf(xi.w - si.w, r.w, si.w);
    ((float4*)g_xk)[i] = ok;
    ((float4*)g_xv)[i] = ov;
    ((float4*)g_xr)[i] = orr;
}

// warp-sized dot of one 16KB row with b; 8-deep manual load batching
__device__ __forceinline__ float row_dot(const float4* __restrict__ A,
                                         const float4* __restrict__ B,
                                         int lane) {
    float s = 0.f;
    // NF4/32 = 32 iterations per lane; batch 8 -> 4 outer steps
    #pragma unroll
    for (int t = 0; t < 4; t++) {
        float4 a[8], b[8];
        #pragma unroll
        for (int u = 0; u < 8; u++) {
            int j = lane + (t * 8 + u) * 32;
            a[u] = __ldg(&A[j]);
            b[u] = __ldg(&B[j]);
        }
        #pragma unroll
        for (int u = 0; u < 8; u++) s += dot4(a[u], b[u]);
    }
    #pragma unroll
    for (int o = 16; o; o >>= 1) s += __shfl_xor_sync(0xffffffffu, s, o);
    return s;
}

// one 1-warp block per (row, matrix). grid = (DD, 3), block = 32
__global__ void __launch_bounds__(32) matvec3_kernel(
        const float* __restrict__ wk, const float* __restrict__ wv,
        const float* __restrict__ wr) {
    const int lane = threadIdx.x;
    const int row  = blockIdx.x;
    const int m    = blockIdx.y;

    const float* W = (m == 0) ? wk   : (m == 1) ? wv   : wr;
    const float* B = (m == 0) ? g_xk : (m == 1) ? g_xv : g_xr;

    float s = row_dot((const float4*)(W + (size_t)row * DD), (const float4*)B, lane);

    if (lane == 0) {
        if (m == 0)      g_k[row] = s;
        else if (m == 1) g_v[row] = s;
        else             g_r[row] = 1.0f / (1.0f + expf(-s));
    }
}

// grid 32 x 128. out: [y | x | new_aa | new_bb | new_pp]
__global__ void wkv_kernel(const float* __restrict__ x,
                           const float* __restrict__ aa,
                           const float* __restrict__ bb,
                           const float* __restrict__ pp,
                           const float* __restrict__ t_decay,
                           const float* __restrict__ t_first,
                           float* __restrict__ out) {
    int i = blockIdx.x * 128 + threadIdx.x;
    if (i >= DD) return;
    float k = g_k[i], v = g_v[i], r = g_r[i];
    float ppi = pp[i], aai = aa[i], bbi = bb[i];

    float ww = t_first[i] + k;
    float p  = fmaxf(ppi, ww);
    float e1 = expf(ppi - p);
    float e2 = expf(ww - p);
    float a  = fmaf(e1, aai, e2 * v);
    float b  = fmaf(e1, bbi, e2);
    g_rv[i]  = r * (a / b);

    float ww2 = ppi + t_decay[i];
    float p2  = fmaxf(ww2, k);
    float e1b = expf(ww2 - p2);
    float e2b = expf(k - p2);

    out[DD + i]     = x[i];
    out[2 * DD + i] = fmaf(e1b, aai, e2b * v);
    out[3 * DD + i] = fmaf(e1b, bbi, e2b);
    out[4 * DD + i] = p2;
}

// one 1-warp block per row. grid = DD, block = 32
__global__ void __launch_bounds__(32) matvec_out_kernel(
        const float* __restrict__ wo, float* __restrict__ out) {
    const int lane = threadIdx.x;
    const int row  = blockIdx.x;

    float s = row_dot((const float4*)(wo + (size_t)row * DD),
                      (const float4*)g_rv, lane);

    if (lane == 0) out[row] = s;
}

extern "C" void kernel_launch(void* const* d_in, const int* in_sizes, int n_in,
                              void* d_out, int out_size) {
    const float* x       = (const float*)d_in[0];
    const float* sxx     = (const float*)d_in[1];
    const float* aa      = (const float*)d_in[2];
    const float* bb      = (const float*)d_in[3];
    const float* pp      = (const float*)d_in[4];
    const float* w_key   = (const float*)d_in[5];
    const float* w_val   = (const float*)d_in[6];
    const float* w_rec   = (const float*)d_in[7];
    const float* w_out   = (const float*)d_in[8];
    const float* t_decay = (const float*)d_in[9];
    const float* t_first = (const float*)d_in[10];
    const float* t_mix_k = (const float*)d_in[11];
    const float* t_mix_v = (const float*)d_in[12];
    const float* t_mix_r = (const float*)d_in[13];
    float* out = (float*)d_out;

    mix_kernel<<<16, 64>>>(x, sxx, t_mix_k, t_mix_v, t_mix_r);
    matvec3_kernel<<<dim3(DD, 3), 32>>>(w_key, w_val, w_rec);
    wkv_kernel<<<32, 128>>>(x, aa, bb, pp, t_decay, t_first, out);
    matvec_out_kernel<<<DD, 32>>>(w_out, out);
}